// round 3
// baseline (speedup 1.0000x reference)
#include <cuda_runtime.h>
#include <cuda_bf16.h>
#include <stdint.h>

#define B_SZ 8192
#define T_SZ 64
#define E_SZ 64
#define C_SZ 20
#define W_SZ 30
#define COLS (W_SZ * E_SZ)     // 1920
#define NBINS 4096
#define OUT_ROW 320

// Scratch (allocation-free rule: __device__ globals)
__device__ float g_lastT[(size_t)COLS * B_SZ];   // [w*64+e][b]
__device__ float g_rankT[(size_t)COLS * B_SZ];   // [w*64+e][b]

// ---------------------------------------------------------------------------
// K0: gather x[b, 34+w, e] -> lastT[(w*64+e)*8192 + b]   (tiled transpose)
// grid (32, 8, 30), block 256
// ---------------------------------------------------------------------------
__global__ __launch_bounds__(256) void k_gather(const float* __restrict__ x) {
    __shared__ float tile[256][9];           // pad 9 to dodge bank conflicts
    const int b0 = blockIdx.x * 256;
    const int e0 = blockIdx.y * 8;
    const int w  = blockIdx.z;
    const int t  = threadIdx.x;

    const float* p = x + (size_t)(b0 + t) * (T_SZ * E_SZ) + (34 + w) * E_SZ + e0;
    float4 a = *reinterpret_cast<const float4*>(p);
    float4 b = *reinterpret_cast<const float4*>(p + 4);
    tile[t][0] = a.x; tile[t][1] = a.y; tile[t][2] = a.z; tile[t][3] = a.w;
    tile[t][4] = b.x; tile[t][5] = b.y; tile[t][6] = b.z; tile[t][7] = b.w;
    __syncthreads();

    #pragma unroll
    for (int eo = 0; eo < 8; eo++) {
        g_lastT[(size_t)(w * E_SZ + e0 + eo) * B_SZ + b0 + t] = tile[t][eo];
    }
}

// ---------------------------------------------------------------------------
// K1: exact descending rank (stable ties by index) per column via
// uniform bucketing + histogram + scan + scatter + within-bucket refine.
// grid 1920, block 256, dynamic smem = hist(16K) + keys2(64K) + scan(128B)
// ---------------------------------------------------------------------------
__device__ __forceinline__ int bucket_desc(float v) {
    float f = (v + 4.0f) * (NBINS / 8.0f);
    int k = (int)f;                         // trunc; clamp below
    k = max(0, min(NBINS - 1, k));
    return (NBINS - 1) - k;                 // descending-value bucket order
}

__device__ __forceinline__ unsigned long long make_key(float v, int i) {
    unsigned u  = __float_as_uint(v);
    unsigned au = (u & 0x80000000u) ? ~u : (u | 0x80000000u); // ascending monotone
    unsigned dk = ~au;                                        // descending monotone
    return ((unsigned long long)dk << 32) | (unsigned)i;      // tie: smaller b first
}

__global__ __launch_bounds__(256) void k_rank() {
    extern __shared__ unsigned char sm[];
    unsigned int*       hist  = reinterpret_cast<unsigned int*>(sm);                   // NBINS u32
    unsigned long long* keys2 = reinterpret_cast<unsigned long long*>(sm + NBINS * 4); // 8192 u64
    unsigned int*       stmp  = reinterpret_cast<unsigned int*>(sm + NBINS * 4 + B_SZ * 8); // 32 u32

    const int c = blockIdx.x;
    const int t = threadIdx.x;
    const float* __restrict__ col = g_lastT + (size_t)c * B_SZ;

    #pragma unroll
    for (int j = t; j < NBINS; j += 256) hist[j] = 0u;
    __syncthreads();

    // load column once into registers; build histogram
    float vr[32];
    #pragma unroll
    for (int j = 0; j < 32; j++) {
        vr[j] = col[j * 256 + t];
        atomicAdd(&hist[bucket_desc(vr[j])], 1u);
    }
    __syncthreads();

    // in-place exclusive scan of hist[0..NBINS)
    unsigned int loc[16];
    const int base = t * 16;
    unsigned int sum = 0;
    #pragma unroll
    for (int i = 0; i < 16; i++) { loc[i] = hist[base + i]; sum += loc[i]; }
    const unsigned lane = t & 31, wid = t >> 5;
    unsigned int inc = sum;
    #pragma unroll
    for (int o = 1; o < 32; o <<= 1) {
        unsigned int n = __shfl_up_sync(0xffffffffu, inc, o);
        if (lane >= (unsigned)o) inc += n;
    }
    if (lane == 31) stmp[wid] = inc;
    __syncthreads();
    if (t < 32) {
        unsigned int wv = (t < 8) ? stmp[t] : 0u;
        #pragma unroll
        for (int o = 1; o < 8; o <<= 1) {
            unsigned int n = __shfl_up_sync(0xffffffffu, wv, o);
            if (t >= o) wv += n;
        }
        if (t < 8) stmp[t] = wv;
    }
    __syncthreads();
    unsigned int excl = inc - sum + (wid ? stmp[wid - 1] : 0u);
    unsigned int run = excl;
    #pragma unroll
    for (int i = 0; i < 16; i++) { hist[base + i] = run; run += loc[i]; }
    __syncthreads();

    // scatter keys into bucket-grouped order (hist becomes inclusive ends)
    #pragma unroll
    for (int j = 0; j < 32; j++) {
        int i = j * 256 + t;
        int kd = bucket_desc(vr[j]);
        unsigned pos = atomicAdd(&hist[kd], 1u);
        keys2[pos] = make_key(vr[j], i);
    }
    __syncthreads();

    // refine: rank = (#elems in smaller buckets) + (#same-bucket keys < mine)
    float* __restrict__ rout = g_rankT + (size_t)c * B_SZ;
    #pragma unroll
    for (int j = 0; j < 32; j++) {
        int i = j * 256 + t;
        int kd = bucket_desc(vr[j]);
        unsigned long long key = make_key(vr[j], i);
        unsigned start = kd ? hist[kd - 1] : 0u;
        unsigned end   = hist[kd];
        unsigned cnt   = 0;
        for (unsigned p = start; p < end; p++) cnt += (keys2[p] < key) ? 1u : 0u;
        rout[i] = (float)(start + cnt) * (1.0f / (float)B_SZ);
    }
}

// ---------------------------------------------------------------------------
// K2: transpose ranks into out[b][w][128+e]   grid (256, 30), block 256
// ---------------------------------------------------------------------------
__global__ __launch_bounds__(256) void k_merge(float* __restrict__ out) {
    __shared__ float st[64][33];
    const int b0 = blockIdx.x * 32;
    const int w  = blockIdx.y;
    const int t  = threadIdx.x;

    #pragma unroll
    for (int ii = 0; ii < 8; ii++) {
        int idx = t + 256 * ii;          // 0..2047
        int e  = idx >> 5;               // 0..63
        int bb = idx & 31;               // 0..31
        st[e][bb] = g_rankT[(size_t)(w * E_SZ + e) * B_SZ + b0 + bb];
    }
    __syncthreads();
    #pragma unroll
    for (int ii = 0; ii < 8; ii++) {
        int idx = t + 256 * ii;
        int e  = idx & 63;
        int bb = idx >> 6;
        __stcs(&out[((size_t)(b0 + bb) * W_SZ + w) * OUT_ROW + 128 + e], st[e][bb]);
    }
}

// ---------------------------------------------------------------------------
// K3: mean / std(ddof=1) / max / min over 20-wide sliding windows.
// grid 2048, block 256 : thread = (b_local in 0..3, e in 0..63)
// van Herk / Gil-Werman sliding max-min; incremental sums for mean/std.
// ---------------------------------------------------------------------------
__global__ __launch_bounds__(256) void k_stats(const float* __restrict__ x,
                                               float* __restrict__ out) {
    const int b = blockIdx.x * 4 + (threadIdx.x >> 6);
    const int e = threadIdx.x & 63;

    const float* __restrict__ xp = x + (size_t)b * (T_SZ * E_SZ) + e;
    float v[49];
    #pragma unroll
    for (int i = 0; i < 49; i++) v[i] = xp[(15 + i) * E_SZ];

    float* __restrict__ orow = out + (size_t)b * W_SZ * OUT_ROW + e;

    // ---- mean / std ----
    {
        float s = 0.f, q = 0.f;
        #pragma unroll
        for (int i = 0; i < 20; i++) { s += v[i]; q += v[i] * v[i]; }
        #pragma unroll
        for (int w = 0; w < 30; w++) {
            float mean = s * (1.0f / 20.0f);
            float var  = (q - s * s * (1.0f / 20.0f)) * (1.0f / 19.0f);
            var = fmaxf(var, 0.0f);
            __stcs(&orow[(size_t)w * OUT_ROW + 0],  mean);
            __stcs(&orow[(size_t)w * OUT_ROW + 64], sqrtf(var));
            if (w < 29) {
                float add = v[w + 20], sub = v[w];
                s += add - sub;
                q += add * add - sub * sub;
            }
        }
    }

    // ---- sliding max (van Herk: blocks [0,20), [20,40), [40,49)) ----
    {
        float Rm[29], Lm[30];
        Rm[0] = v[20];
        #pragma unroll
        for (int p = 21; p < 40; p++) Rm[p - 20] = fmaxf(Rm[p - 21], v[p]);
        Rm[20] = v[40];
        #pragma unroll
        for (int p = 41; p < 49; p++) Rm[p - 20] = fmaxf(Rm[p - 21], v[p]);
        Lm[19] = v[19];
        #pragma unroll
        for (int p = 18; p >= 0; p--) Lm[p] = fmaxf(Lm[p + 1], v[p]);
        {
            float run = v[39];
            #pragma unroll
            for (int p = 38; p >= 20; p--) {
                run = fmaxf(run, v[p]);
                if (p <= 29) Lm[p] = run;
            }
        }
        #pragma unroll
        for (int w = 0; w < 30; w++) {
            float m = (w == 0 || w == 20) ? Lm[w] : fmaxf(Lm[w], Rm[w - 1]);
            __stcs(&orow[(size_t)w * OUT_ROW + 192], m);
        }
    }

    // ---- sliding min ----
    {
        float Rm[29], Lm[30];
        Rm[0] = v[20];
        #pragma unroll
        for (int p = 21; p < 40; p++) Rm[p - 20] = fminf(Rm[p - 21], v[p]);
        Rm[20] = v[40];
        #pragma unroll
        for (int p = 41; p < 49; p++) Rm[p - 20] = fminf(Rm[p - 21], v[p]);
        Lm[19] = v[19];
        #pragma unroll
        for (int p = 18; p >= 0; p--) Lm[p] = fminf(Lm[p + 1], v[p]);
        {
            float run = v[39];
            #pragma unroll
            for (int p = 38; p >= 20; p--) {
                run = fminf(run, v[p]);
                if (p <= 29) Lm[p] = run;
            }
        }
        #pragma unroll
        for (int w = 0; w < 30; w++) {
            float m = (w == 0 || w == 20) ? Lm[w] : fminf(Lm[w], Rm[w - 1]);
            __stcs(&orow[(size_t)w * OUT_ROW + 256], m);
        }
    }
}

// ---------------------------------------------------------------------------
extern "C" void kernel_launch(void* const* d_in, const int* in_sizes, int n_in,
                              void* d_out, int out_size) {
    const float* x = (const float*)d_in[0];
    float* out = (float*)d_out;

    const int rank_smem = NBINS * 4 + B_SZ * 8 + 32 * 4;   // 82048 bytes
    cudaFuncSetAttribute(k_rank, cudaFuncAttributeMaxDynamicSharedMemorySize,
                         rank_smem);

    k_gather<<<dim3(32, 8, 30), 256>>>(x);
    k_rank<<<COLS, 256, rank_smem>>>();
    k_merge<<<dim3(256, 30), 256>>>(out);
    k_stats<<<2048, 256>>>(x, out);
}

// round 6
// speedup vs baseline: 1.0007x; 1.0007x over previous
#include <cuda_runtime.h>
#include <cuda_bf16.h>
#include <stdint.h>

#define B_SZ 8192
#define T_SZ 64
#define E_SZ 64
#define C_SZ 20
#define W_SZ 30
#define COLS (W_SZ * E_SZ)     // 1920
#define NBINS 4096
#define OUT_ROW 320

// Scratch (allocation-free rule: __device__ globals)
__device__ float g_lastT[(size_t)COLS * B_SZ];   // [w*64+e][b]
__device__ float g_rankT[(size_t)COLS * B_SZ];   // [w*64+e][b]

// ---------------------------------------------------------------------------
// K0: gather x[b, 34+w, e] -> lastT[(w*64+e)*8192 + b]   (tiled transpose)
// grid (32, 8, 30), block 256
// ---------------------------------------------------------------------------
__global__ __launch_bounds__(256) void k_gather(const float* __restrict__ x) {
    __shared__ float tile[256][9];           // pad 9 to dodge bank conflicts
    const int b0 = blockIdx.x * 256;
    const int e0 = blockIdx.y * 8;
    const int w  = blockIdx.z;
    const int t  = threadIdx.x;

    const float* p = x + (size_t)(b0 + t) * (T_SZ * E_SZ) + (34 + w) * E_SZ + e0;
    float4 a = *reinterpret_cast<const float4*>(p);
    float4 b = *reinterpret_cast<const float4*>(p + 4);
    tile[t][0] = a.x; tile[t][1] = a.y; tile[t][2] = a.z; tile[t][3] = a.w;
    tile[t][4] = b.x; tile[t][5] = b.y; tile[t][6] = b.z; tile[t][7] = b.w;
    __syncthreads();

    #pragma unroll
    for (int eo = 0; eo < 8; eo++) {
        g_lastT[(size_t)(w * E_SZ + e0 + eo) * B_SZ + b0 + t] = tile[t][eo];
    }
}

// ---------------------------------------------------------------------------
// K1: exact descending rank (stable ties by index) per column.
// Bucket histogram (1 ATOMS/elem, arrival index captured from atomic return),
// exclusive scan -> immutable starts, atomic-free scatter, in-bucket refine.
// grid 1920, block 256, dyn smem = hist(16K) + keys2(64K) + stmp
// ---------------------------------------------------------------------------
__device__ __forceinline__ int bucket_desc(float v) {
    float f = (v + 4.0f) * (NBINS / 8.0f);
    int k = (int)f;                         // trunc; clamp below
    k = max(0, min(NBINS - 1, k));
    return (NBINS - 1) - k;                 // descending-value bucket order
}

__device__ __forceinline__ unsigned long long make_key(float v, int i) {
    unsigned u  = __float_as_uint(v);
    unsigned au = (u & 0x80000000u) ? ~u : (u | 0x80000000u); // ascending monotone
    unsigned dk = ~au;                                        // descending monotone
    return ((unsigned long long)dk << 32) | (unsigned)i;      // tie: smaller b first
}

__global__ __launch_bounds__(256) void k_rank() {
    extern __shared__ unsigned char sm[];
    unsigned int*       hist  = reinterpret_cast<unsigned int*>(sm);                   // NBINS u32
    unsigned long long* keys2 = reinterpret_cast<unsigned long long*>(sm + NBINS * 4); // 8192 u64
    unsigned int*       stmp  = reinterpret_cast<unsigned int*>(sm + NBINS * 4 + B_SZ * 8); // 32 u32

    const int c = blockIdx.x;
    const int t = threadIdx.x;
    const float* __restrict__ col = g_lastT + (size_t)c * B_SZ;

    #pragma unroll
    for (int j = t; j < NBINS; j += 256) hist[j] = 0u;
    __syncthreads();

    // pass 1: histogram; atomic RETURN VALUE = arrival index within bucket
    float vr[32];
    int   arr[32];
    #pragma unroll
    for (int j = 0; j < 32; j++) {
        vr[j]  = col[j * 256 + t];
        arr[j] = (int)atomicAdd(&hist[bucket_desc(vr[j])], 1u);
    }
    __syncthreads();

    // exclusive scan of hist -> hist[bin] = immutable exclusive start
    unsigned int loc[16];
    const int base = t * 16;
    unsigned int sum = 0;
    #pragma unroll
    for (int i = 0; i < 16; i++) { loc[i] = hist[base + i]; sum += loc[i]; }
    const unsigned lane = t & 31, wid = t >> 5;
    unsigned int inc = sum;
    #pragma unroll
    for (int o = 1; o < 32; o <<= 1) {
        unsigned int n = __shfl_up_sync(0xffffffffu, inc, o);
        if (lane >= (unsigned)o) inc += n;
    }
    if (lane == 31) stmp[wid] = inc;
    __syncthreads();
    if (t < 32) {
        unsigned int wv = (t < 8) ? stmp[t] : 0u;
        #pragma unroll
        for (int o = 1; o < 8; o <<= 1) {
            unsigned int n = __shfl_up_sync(0xffffffffu, wv, o);
            if (t >= o) wv += n;
        }
        if (t < 8) stmp[t] = wv;
    }
    __syncthreads();
    unsigned int excl = inc - sum + (wid ? stmp[wid - 1] : 0u);
    unsigned int run = excl;
    #pragma unroll
    for (int i = 0; i < 16; i++) { hist[base + i] = run; run += loc[i]; }
    __syncthreads();

    // scatter (NO atomics): pos = start[bin] + arrival
    #pragma unroll
    for (int j = 0; j < 32; j++) {
        int i  = j * 256 + t;
        int kd = bucket_desc(vr[j]);
        keys2[hist[kd] + (unsigned)arr[j]] = make_key(vr[j], i);
    }
    __syncthreads();

    // refine: rank = start + (#same-bucket keys < mine)
    float* __restrict__ rout = g_rankT + (size_t)c * B_SZ;
    #pragma unroll
    for (int j = 0; j < 32; j++) {
        int i  = j * 256 + t;
        int kd = bucket_desc(vr[j]);
        unsigned long long key = make_key(vr[j], i);
        unsigned start = hist[kd];
        unsigned end   = (kd < NBINS - 1) ? hist[kd + 1] : (unsigned)B_SZ;
        unsigned cnt   = 0;
        for (unsigned p = start; p < end; p++) cnt += (keys2[p] < key) ? 1u : 0u;
        rout[i] = (float)(start + cnt) * (1.0f / (float)B_SZ);
    }
}

// ---------------------------------------------------------------------------
// K2: transpose ranks into out[b][w][128+e]   grid (256, 30), block 256
// ---------------------------------------------------------------------------
__global__ __launch_bounds__(256) void k_merge(float* __restrict__ out) {
    __shared__ float st[64][33];
    const int b0 = blockIdx.x * 32;
    const int w  = blockIdx.y;
    const int t  = threadIdx.x;

    #pragma unroll
    for (int ii = 0; ii < 8; ii++) {
        int idx = t + 256 * ii;          // 0..2047
        int e  = idx >> 5;               // 0..63
        int bb = idx & 31;               // 0..31
        st[e][bb] = g_rankT[(size_t)(w * E_SZ + e) * B_SZ + b0 + bb];
    }
    __syncthreads();
    #pragma unroll
    for (int ii = 0; ii < 8; ii++) {
        int idx = t + 256 * ii;
        int e  = idx & 63;
        int bb = idx >> 6;
        __stcs(&out[((size_t)(b0 + bb) * W_SZ + w) * OUT_ROW + 128 + e], st[e][bb]);
    }
}

// ---------------------------------------------------------------------------
// K3: mean / std(ddof=1) / max / min over 20-wide sliding windows.
// grid 2048, block 256 : thread = (b_local in 0..3, e in 0..63)
// __launch_bounds__(256,3): force <=85 regs -> 3 CTAs/SM for more MLP.
// ---------------------------------------------------------------------------
__global__ __launch_bounds__(256, 3) void k_stats(const float* __restrict__ x,
                                                  float* __restrict__ out) {
    const int b = blockIdx.x * 4 + (threadIdx.x >> 6);
    const int e = threadIdx.x & 63;

    const float* __restrict__ xp = x + (size_t)b * (T_SZ * E_SZ) + e;
    float v[49];
    #pragma unroll
    for (int i = 0; i < 49; i++) v[i] = xp[(15 + i) * E_SZ];

    float* __restrict__ orow = out + (size_t)b * W_SZ * OUT_ROW + e;

    // ---- mean / std ----
    {
        float s = 0.f, q = 0.f;
        #pragma unroll
        for (int i = 0; i < 20; i++) { s += v[i]; q += v[i] * v[i]; }
        #pragma unroll
        for (int w = 0; w < 30; w++) {
            float mean = s * (1.0f / 20.0f);
            float var  = (q - s * s * (1.0f / 20.0f)) * (1.0f / 19.0f);
            var = fmaxf(var, 0.0f);
            __stcs(&orow[(size_t)w * OUT_ROW + 0],  mean);
            __stcs(&orow[(size_t)w * OUT_ROW + 64], sqrtf(var));
            if (w < 29) {
                float add = v[w + 20], sub = v[w];
                s += add - sub;
                q += add * add - sub * sub;
            }
        }
    }

    // ---- sliding max (van Herk: blocks [0,20), [20,40), [40,49)) ----
    {
        float Rm[29], Lm[30];
        Rm[0] = v[20];
        #pragma unroll
        for (int p = 21; p < 40; p++) Rm[p - 20] = fmaxf(Rm[p - 21], v[p]);
        Rm[20] = v[40];
        #pragma unroll
        for (int p = 41; p < 49; p++) Rm[p - 20] = fmaxf(Rm[p - 21], v[p]);
        Lm[19] = v[19];
        #pragma unroll
        for (int p = 18; p >= 0; p--) Lm[p] = fmaxf(Lm[p + 1], v[p]);
        {
            float run = v[39];
            #pragma unroll
            for (int p = 38; p >= 20; p--) {
                run = fmaxf(run, v[p]);
                if (p <= 29) Lm[p] = run;
            }
        }
        #pragma unroll
        for (int w = 0; w < 30; w++) {
            float m = (w == 0 || w == 20) ? Lm[w] : fmaxf(Lm[w], Rm[w - 1]);
            __stcs(&orow[(size_t)w * OUT_ROW + 192], m);
        }
    }

    // ---- sliding min ----
    {
        float Rm[29], Lm[30];
        Rm[0] = v[20];
        #pragma unroll
        for (int p = 21; p < 40; p++) Rm[p - 20] = fminf(Rm[p - 21], v[p]);
        Rm[20] = v[40];
        #pragma unroll
        for (int p = 41; p < 49; p++) Rm[p - 20] = fminf(Rm[p - 21], v[p]);
        Lm[19] = v[19];
        #pragma unroll
        for (int p = 18; p >= 0; p--) Lm[p] = fminf(Lm[p + 1], v[p]);
        {
            float run = v[39];
            #pragma unroll
            for (int p = 38; p >= 20; p--) {
                run = fminf(run, v[p]);
                if (p <= 29) Lm[p] = run;
            }
        }
        #pragma unroll
        for (int w = 0; w < 30; w++) {
            float m = (w == 0 || w == 20) ? Lm[w] : fminf(Lm[w], Rm[w - 1]);
            __stcs(&orow[(size_t)w * OUT_ROW + 256], m);
        }
    }
}

// ---------------------------------------------------------------------------
extern "C" void kernel_launch(void* const* d_in, const int* in_sizes, int n_in,
                              void* d_out, int out_size) {
    const float* x = (const float*)d_in[0];
    float* out = (float*)d_out;

    const int rank_smem = NBINS * 4 + B_SZ * 8 + 32 * 4;   // 82048 bytes
    cudaFuncSetAttribute(k_rank, cudaFuncAttributeMaxDynamicSharedMemorySize,
                         rank_smem);

    k_gather<<<dim3(32, 8, 30), 256>>>(x);
    k_rank<<<COLS, 256, rank_smem>>>();
    k_merge<<<dim3(256, 30), 256>>>(out);
    k_stats<<<2048, 256>>>(x, out);
}